// round 14
// baseline (speedup 1.0000x reference)
#include <cuda_runtime.h>
#include <cstdint>

// LocalPatternExtractor: reference forward output is identically zero.
//   quantize clips mem <= 127/128 < THRESHOLD=1.0 -> spike always 0 ->
//   out = zeros(16,256,5000), reg_loss = 0. (rel_err = 0.0, rounds 2-13.)
//
// Established ladder (82 MB zero-fill):
//   - SM store paths (STG.128/256, TMA bulk, combos): chip cap ~5.8 TB/s.
//   - Graph memset node: CE-class fill, ~6.7 TB/s, own port.
//   - R13 PROVED the paths add: kernel branch ran 4.4 TB/s concurrent with
//     memset (aggregate ~11 TB/s). But 47/53 split left the kernel branch as
//     an 8.7us critical path, and the 6-node fork-join graph carries ~7.5us
//     replay overhead -> 16.2 total vs 14.8 single-memset.
// This round: rebalance split to equalize branch times:
//   f_memset = 6.7/(6.7+4.4) ~ 0.61 -> both branches ~7.2us.

static cudaStream_t g_s1 = nullptr;
static cudaEvent_t g_ev_fork = nullptr;
static cudaEvent_t g_ev_join = nullptr;

namespace {
struct StreamInit {
    StreamInit() {
        cudaStreamCreateWithFlags(&g_s1, cudaStreamNonBlocking);
        cudaEventCreateWithFlags(&g_ev_fork, cudaEventDisableTiming);
        cudaEventCreateWithFlags(&g_ev_join, cudaEventDisableTiming);
    }
};
StreamInit g_stream_init;
}  // namespace

__global__ void __launch_bounds__(256)
zero_fill_256(double* __restrict__ out, size_t n_chunks,
              float* __restrict__ tail, int n_tail) {
    const size_t stride = (size_t)gridDim.x * blockDim.x;
    size_t i = (size_t)blockIdx.x * blockDim.x + threadIdx.x;
    const double z = 0.0;
    for (; i < n_chunks; i += stride) {
        double* p = out + i * 4;
        asm volatile("st.global.v4.f64 [%0], {%1, %1, %1, %1};"
                     :: "l"(p), "d"(z) : "memory");
    }
    size_t t = (size_t)blockIdx.x * blockDim.x + threadIdx.x;
    if (t < (size_t)n_tail) {
        tail[t] = 0.f;
    }
}

extern "C" void kernel_launch(void* const* d_in, const int* in_sizes, int n_in,
                              void* d_out, int out_size) {
    (void)d_in; (void)in_sizes; (void)n_in;

    char* p = (char*)d_out;
    size_t bytes = (size_t)out_size * sizeof(float);     // 81,920,004
    // 61% to the CE memset path, 39% to the SM kernel path (rate-balanced).
    size_t ms_bytes = ((size_t)(bytes * 0.61)) & ~(size_t)31;
    size_t rest = bytes - ms_bytes;
    size_t n_chunks = rest / 32;                         // 32B STG.256 chunks
    size_t covered = ms_bytes + n_chunks * 32;
    int n_tail = (int)((bytes - covered) / 4);           // leftover floats
    float* tail_ptr = (float*)(p + covered);

    // Fork side stream off the capture stream.
    cudaEventRecord(g_ev_fork, 0);
    cudaStreamWaitEvent(g_s1, g_ev_fork, 0);

    // Parallel branches: CE fill on stream 0, SM stores on s1.
    cudaMemsetAsync(p, 0, ms_bytes, 0);
    zero_fill_256<<<1184, 256, 0, g_s1>>>((double*)(p + ms_bytes), n_chunks,
                                          tail_ptr, n_tail);

    // Join.
    cudaEventRecord(g_ev_join, g_s1);
    cudaStreamWaitEvent(0, g_ev_join, 0);
}

// round 16
// speedup vs baseline: 1.1123x; 1.1123x over previous
#include <cuda_runtime.h>
#include <cstdint>

// LocalPatternExtractor_82222853915140 — FINAL kernel.
//
// The reference forward output is identically zero:
//   quantize_pot_ste clips round(mem*128) to [-128, 127], so the quantized
//   membrane potential is at most 127/128 = 0.9921875 < THRESHOLD (1.0).
//   The forward spike value is the hard indicator (mem >= 1.0) — always
//   false — so acc stays 0 over all 4 timesteps: out = zeros(16,256,5000),
//   reg_loss = 0.01 * 0 = 0. (Confirmed rel_err = 0.0 across rounds 2-14.)
//
// Hence the problem reduces to an 82 MB zero-fill. Design space mapped over
// rounds 2-14 (kernel-level write bandwidth on sm_103a):
//   - STG.128 grid-stride:        4.0 TB/s
//   - STG.256 (st.global.v4.f64): 5.7 TB/s
//   - TMA bulk (cp.async.bulk):   5.8 TB/s
//   - STG.256 + TMA concurrently: 5.7 TB/s  -> hard chip write-acceptance
//     cap ~5.8 TB/s for ALL SM-originated stores (ncu "L2=48%" = saturated
//     write port; dirty set stays in the 126MB L2, DRAM ~idle).
//   - memset-node || kernel-node fork-join: paths DO add (~9.8 TB/s agg),
//     but parallel-branch graph replay overhead (~7.5us) makes best-case
//     ~15.9us -> cannot beat the single node.
//   - single graph memset node: fastest fill path (CE-class, ~6+ TB/s) AND
//     the cheapest replay -> 14.8us end-to-end. Optimal.

extern "C" void kernel_launch(void* const* d_in, const int* in_sizes, int n_in,
                              void* d_out, int out_size) {
    (void)d_in; (void)in_sizes; (void)n_in;
    // Zero the entire fp32 output (20,480,000 spike rates + reg_loss scalar).
    cudaMemsetAsync(d_out, 0, (size_t)out_size * sizeof(float), 0);
}